// round 15
// baseline (speedup 1.0000x reference)
#include <cuda_runtime.h>
#include <cuda_fp16.h>
#include <math.h>

#define B4     4
#define FFRAMES 16
#define VV     196
#define DD     768
#define NX     25088          // T*F*V
#define NZ     64
#define HH     8
#define INNER  512
#define QKV_LD 1536           // 3*INNER
#define FFH    3072
#define LAYERS 6
#define SPLITS 14             // split-K for AV gemm (784/14 = 56 chunks)
#define W2SPL  8              // split-K for Wo / W2 gemms
#define QKVSPL 4              // split-K for qkv gemm
#define QKV_PSTR ((size_t)B4 * NZ * QKV_LD)

// ---------------- scratch (static device memory; no allocations) ----------------
__device__ __align__(256) __half g_nxh[(size_t)B4 * NX * DD];        // fp16 normalized x
__device__ __align__(256) __half g_nxTh[(size_t)B4 * DD * NX];       // transposed
__device__ __align__(256) __half g_Ph[(size_t)B4 * INNER * NX];      // exp(sim) fp16 (GEMM1 epilogue)
__device__ __align__(256) __half g_QKh[B4 * INNER * DD];             // QK fp16
__device__ float g_Plat[B4 * INNER * NZ];
__device__ float g_qbias[B4 * INNER];
__device__ float g_rowZ[B4 * INNER];
__device__ float g_sumPx[B4 * INNER];
__device__ __align__(256) float g_AVpart[(size_t)B4 * SPLITS * INNER * DD];
__device__ __align__(256) float g_AV[B4 * INNER * DD];
__device__ __align__(256) float g_qkvpart[(size_t)QKVSPL * B4 * NZ * QKV_LD];
__device__ __align__(256) float g_W2part[(size_t)W2SPL * B4 * NZ * DD];  // Wo & W2 partials (time-shared)
__device__ float g_Wkf[LAYERS * DD * INNER];
__device__ float g_Wvf[LAYERS * DD * INNER];
__device__ float g_bk[LAYERS * INNER];
__device__ float g_bv[LAYERS * INNER];
__device__ float g_lat[B4 * NZ * DD];
// fp16 operands for small tensor GEMMs (all layers precomputed)
__device__ __align__(256) __half g_lnlat_h[B4 * NZ * DD];
__device__ __align__(256) __half g_hln_h[B4 * NZ * DD];
__device__ __align__(256) __half g_attnout_h[B4 * NZ * INNER];
__device__ __align__(256) __half g_h1h[B4 * NZ * FFH];
__device__ __align__(256) __half g_WqkvT[(size_t)LAYERS * QKV_LD * DD];
__device__ __align__(256) __half g_WoT[(size_t)LAYERS * DD * INNER];
__device__ __align__(256) __half g_W1T[(size_t)LAYERS * FFH * DD];
__device__ __align__(256) __half g_W2T[(size_t)LAYERS * DD * FFH];

// ---------------- PTX helpers ----------------
__device__ __forceinline__ unsigned smem_u32(const void* p) {
    unsigned a;
    asm("{ .reg .u64 t; cvta.to.shared.u64 t, %1; cvt.u32.u64 %0, t; }" : "=r"(a) : "l"(p));
    return a;
}
__device__ __forceinline__ void cpasync16(unsigned dst, const void* src) {
    asm volatile("cp.async.cg.shared.global [%0], [%1], 16;" :: "r"(dst), "l"(src) : "memory");
}
__device__ __forceinline__ void mma16816h(float* c, const unsigned* a, const unsigned* b) {
    asm volatile(
        "mma.sync.aligned.m16n8k16.row.col.f32.f16.f16.f32 "
        "{%0,%1,%2,%3}, {%4,%5,%6,%7}, {%8,%9}, {%0,%1,%2,%3};"
        : "+f"(c[0]), "+f"(c[1]), "+f"(c[2]), "+f"(c[3])
        : "r"(a[0]), "r"(a[1]), "r"(a[2]), "r"(a[3]), "r"(b[0]), "r"(b[1]));
}
__device__ __forceinline__ void ldmx4(unsigned* r, unsigned addr) {
    asm volatile("ldmatrix.sync.aligned.m8n8.x4.shared.b16 {%0,%1,%2,%3}, [%4];"
        : "=r"(r[0]), "=r"(r[1]), "=r"(r[2]), "=r"(r[3]) : "r"(addr));
}

// ---------------- reductions / misc ----------------
__device__ __forceinline__ float block_red256(float v, int is_max) {
    __shared__ float sm[8];
    int lane = threadIdx.x & 31, w = threadIdx.x >> 5;
#pragma unroll
    for (int o = 16; o; o >>= 1) {
        float t = __shfl_xor_sync(0xffffffffu, v, o);
        v = is_max ? fmaxf(v, t) : v + t;
    }
    __syncthreads();
    if (lane == 0) sm[w] = v;
    __syncthreads();
    if (w == 0) {
        v = sm[lane & 7];
#pragma unroll
        for (int o = 4; o; o >>= 1) {
            float t = __shfl_xor_sync(0xffffffffu, v, o);
            v = is_max ? fmaxf(v, t) : v + t;
        }
        if (lane == 0) sm[0] = v;
    }
    __syncthreads();
    return sm[0];
}

__device__ __forceinline__ float gelu_exact(float x) {
    return 0.5f * x * (1.0f + erff(x * 0.7071067811865476f));
}

// ---------------- nx: embeds + LN(no affine) -> fp16 ----------------
__global__ __launch_bounds__(256) void nx_kernel(const float* __restrict__ x,
                                                 const float* __restrict__ femb,
                                                 const float* __restrict__ temb) {
    int row = blockIdx.x;                // b*NX + n
    int n = row % NX;
    int t = n / (FFRAMES * VV);
    int f = (n / VV) % FFRAMES;
    const float* xr = x + (size_t)row * DD;
    float vals[3], s = 0.f;
#pragma unroll
    for (int i = 0; i < 3; i++) {
        int d = threadIdx.x + i * 256;
        float v = xr[d] + femb[f * DD + d] + temb[t * DD + d];
        vals[i] = v; s += v;
    }
    float mean = block_red256(s, 0) * (1.0f / DD);
    float q = 0.f;
#pragma unroll
    for (int i = 0; i < 3; i++) { float dv = vals[i] - mean; q += dv * dv; }
    float var = block_red256(q, 0) * (1.0f / DD);
    float r = rsqrtf(var + 1e-5f);
    __half* o = g_nxh + (size_t)row * DD;
#pragma unroll
    for (int i = 0; i < 3; i++) {
        int d = threadIdx.x + i * 256;
        o[d] = __float2half((vals[i] - mean) * r);
    }
}

// ---------------- tiled transpose: g_nxh -> g_nxTh ----------------
__global__ __launch_bounds__(256) void transpose_kernel() {
    __shared__ __half th[64][66];
    int tok0 = blockIdx.x * 64, d0 = blockIdx.y * 64, b = blockIdx.z;
    const __half* in = g_nxh + (size_t)b * NX * DD;
#pragma unroll
    for (int i = 0; i < 8; i++) {
        int idx = i * 256 + threadIdx.x;
        int r = idx >> 5, c2 = idx & 31;
        __half2 vh = *((const __half2*)(in + (size_t)(tok0 + r) * DD + d0) + c2);
        th[r][c2 * 2] = vh.x; th[r][c2 * 2 + 1] = vh.y;
    }
    __syncthreads();
    __half* out = g_nxTh + (size_t)b * DD * NX;
#pragma unroll
    for (int i = 0; i < 8; i++) {
        int idx = i * 256 + threadIdx.x;
        int r = idx >> 5, c2 = idx & 31;      // r = d row, c2 = tok pair
        __half2 vh; vh.x = th[c2 * 2][r]; vh.y = th[c2 * 2 + 1][r];
        *((__half2*)(out + (size_t)(d0 + r) * NX + tok0) + c2) = vh;
    }
}

// -------- weight transpose+convert: in[K,N] fp32 -> out[N,K] fp16 * scale; z = layer ----
__global__ __launch_bounds__(256) void transpose_w_kernel(const float* __restrict__ in,
                                                          __half* __restrict__ out,
                                                          int K, int N, float scale,
                                                          size_t inLS, size_t outLS) {
    __shared__ __half t[32][33];
    int n0 = blockIdx.x * 32, k0 = blockIdx.y * 32;
    in  += (size_t)blockIdx.z * inLS;
    out += (size_t)blockIdx.z * outLS;
    int tid = threadIdx.x;
#pragma unroll
    for (int i = 0; i < 4; i++) {
        int idx = i * 256 + tid;
        int r = idx >> 5, c = idx & 31;     // r = k-local, c = n-local
        t[r][c] = __float2half(in[(size_t)(k0 + r) * N + n0 + c] * scale);
    }
    __syncthreads();
#pragma unroll
    for (int i = 0; i < 4; i++) {
        int idx = i * 256 + tid;
        int r = idx >> 5, c = idx & 31;     // r = n-local, c = k-local
        out[(size_t)(n0 + r) * K + k0 + c] = t[c][r];
    }
}

// ------ LN over 768 with affine; fp32/fp16 output; optional partial add-back ------
// ADDP: in-value = in[row] + sum of W2SPL partial planes (g_W2part); writes the
// summed residual back to latwb so later consumers see the full value.
template <bool HOUT, bool ADDP>
__global__ __launch_bounds__(256) void ln768_kernel(const float* __restrict__ in,
                                                    const float* __restrict__ gg,
                                                    const float* __restrict__ bb,
                                                    void* __restrict__ outv,
                                                    float* __restrict__ latwb) {
    int row = blockIdx.x;
    const float* xr = in + (size_t)row * DD;
    float vals[3], s = 0.f;
#pragma unroll
    for (int i = 0; i < 3; i++) {
        int d = threadIdx.x + i * 256;
        float v = xr[d];
        if (ADDP) {
#pragma unroll
            for (int p = 0; p < W2SPL; p++)
                v += g_W2part[(size_t)p * (B4 * NZ * DD) + (size_t)row * DD + d];
        }
        vals[i] = v; s += v;
    }
    if (ADDP) {
#pragma unroll
        for (int i = 0; i < 3; i++) {
            int d = threadIdx.x + i * 256;
            latwb[(size_t)row * DD + d] = vals[i];
        }
    }
    float mean = block_red256(s, 0) * (1.0f / DD);
    float q = 0.f;
#pragma unroll
    for (int i = 0; i < 3; i++) { float dv = vals[i] - mean; q += dv * dv; }
    float var = block_red256(q, 0) * (1.0f / DD);
    float r = rsqrtf(var + 1e-5f);
#pragma unroll
    for (int i = 0; i < 3; i++) {
        int d = threadIdx.x + i * 256;
        float v = (vals[i] - mean) * r * gg[d] + bb[d];
        if (HOUT) ((__half*)outv)[(size_t)row * DD + d] = __float2half(v);
        else      ((float*)outv)[(size_t)row * DD + d] = v;
    }
}

__global__ void init_lat_kernel(const float* __restrict__ lat) {
    int idx = blockIdx.x * 256 + threadIdx.x;
    g_lat[idx] = lat[idx % (NZ * DD)];
}

// ---------------- fold LN(media) gamma/beta into Wk/Wv (all layers) ----------------
__global__ void fold_kernel(const float* __restrict__ Wk, const float* __restrict__ Wv,
                            const float* __restrict__ gm) {
    int l = blockIdx.y;
    int idx = blockIdx.x * 256 + threadIdx.x;   // < 768*512
    int d = idx >> 9;
    float g = gm[l * DD + d];
    size_t off = (size_t)l * DD * INNER + idx;
    g_Wkf[off] = g * Wk[off];
    g_Wvf[off] = g * Wv[off];
}

__global__ __launch_bounds__(256) void foldbias_kernel(const float* __restrict__ Wk,
                                                       const float* __restrict__ Wv,
                                                       const float* __restrict__ bm) {
    int e = blockIdx.x, l = blockIdx.y;
    float sk = 0.f, sv = 0.f;
    for (int d = threadIdx.x; d < DD; d += 256) {
        float bb = bm[l * DD + d];
        size_t off = (size_t)l * DD * INNER + (size_t)d * INNER + e;
        sk += bb * Wk[off];
        sv += bb * Wv[off];
    }
    sk = block_red256(sk, 0);
    sv = block_red256(sv, 0);
    if (threadIdx.x == 0) { g_bk[l * INNER + e] = sk; g_bv[l * INNER + e] = sv; }
}

// -- QK (reassociated q@Wkf) -> fp16; sums qkv partials inline; d0==0 does qbias --
__global__ __launch_bounds__(256) void qk_kernel(int l) {
    int d0 = blockIdx.x * 64;
    int h = blockIdx.y;
    int b = blockIdx.z;
    __shared__ float qs[64][65];
    __shared__ float ws[64][65];
    int tid = threadIdx.x;
    const float* Wkf = g_Wkf + (size_t)l * DD * INNER;
#pragma unroll
    for (int i = 0; i < 16; i++) {
        int idx = tid + i * 256;
        int r = idx >> 6, c = idx & 63;
        size_t qoff = (size_t)(b * NZ + r) * QKV_LD + h * 64 + c;
        float qv = 0.f;
#pragma unroll
        for (int p = 0; p < QKVSPL; p++) qv += g_qkvpart[p * QKV_PSTR + qoff];
        qs[r][c] = qv;
        ws[r][c] = Wkf[(size_t)(d0 + r) * INNER + h * 64 + c];
    }
    __syncthreads();
    if (blockIdx.x == 0 && tid < 64) {
        const float* bkp = g_bk + l * INNER + h * 64;
        float qb = 0.f;
#pragma unroll 8
        for (int dh = 0; dh < 64; dh++) qb += qs[tid][dh] * bkp[dh];
        g_qbias[b * INNER + h * 64 + tid] = qb;
    }
    int dl = tid & 63;
    int qg = tid >> 6;
    float acc[16] = {};
    for (int dh = 0; dh < 64; dh++) {
        float w = ws[dl][dh];
#pragma unroll
        for (int i = 0; i < 16; i++) acc[i] += qs[qg * 16 + i][dh] * w;
    }
#pragma unroll
    for (int i = 0; i < 16; i++) {
        int qi = qg * 16 + i;
        g_QKh[((size_t)b * INNER + h * 64 + qi) * DD + d0 + dl] = __float2half(acc[i]);
    }
}

// ---- simlat (latent-key scores; sums qkv partials; runs hidden on side stream) ----
__global__ void simlat_kernel() {
    int t = blockIdx.x * 256 + threadIdx.x;
    int j = t & 63; int row = t >> 6;
    int b = row >> 9, hq = row & 511, h = hq >> 6, qi = hq & 63;
    size_t qoff = (size_t)(b * NZ + qi) * QKV_LD + h * 64;
    size_t koff = (size_t)(b * NZ + j) * QKV_LD + INNER + h * 64;
    float s = 0.f;
#pragma unroll 4
    for (int dh = 0; dh < 64; dh++) {
        float qv = 0.f, kv = 0.f;
#pragma unroll
        for (int p = 0; p < QKVSPL; p++) {
            qv += g_qkvpart[p * QKV_PSTR + qoff + dh];
            kv += g_qkvpart[p * QKV_PSTR + koff + dh];
        }
        s += qv * kv;
    }
    g_Plat[t] = s;
}

// ================= fp16 GEMM via mma.sync + ldmatrix (3-stage pipeline) =======
// ACT: 0 = none, 1 = gelu, 2 = exp (no max-subtraction softmax numerator)
#define PLANE_BYTES 10240
#define STG_BYTES   (2 * PLANE_BYTES)
#define NSTAGE      3
#define GEMM_SMEM   (NSTAGE * STG_BYTES)

template <int ACT, bool ACC, bool HOUT>
__global__ __launch_bounds__(256, 2) void gemm_h_kernel(
    const __half* __restrict__ A, int lda,
    const __half* __restrict__ B, int ldb,
    void* __restrict__ Cv, const float* __restrict__ bias,
    int kTotal, int nsplit, int ldc,
    size_t strideAz, size_t strideBz, size_t strideCz)
{
    extern __shared__ char smem[];
    const unsigned sbase = smem_u32(smem);
    const int tid = threadIdx.x;
    const int lane = tid & 31, w = tid >> 5;
    const int wm = w & 1, wn = w >> 1;
    const int m0 = blockIdx.x * 128, n0 = blockIdx.y * 128;
    const int z = blockIdx.z, b = z / nsplit, s = z % nsplit;
    const int kbeg = s * (kTotal / nsplit);
    const int nch = kTotal / (32 * nsplit);
    const __half* pA = A + (size_t)b * strideAz + (size_t)m0 * lda + kbeg;
    const __half* pB = B + (size_t)b * strideBz + (size_t)n0 * ldb + kbeg;

    float acc[4][4][4];
#pragma unroll
    for (int i = 0; i < 4; i++)
#pragma unroll
        for (int j = 0; j < 4; j++)
#pragma unroll
            for (int k = 0; k < 4; k++) acc[i][j][k] = 0.f;

#define LOAD_STAGE(bufi, chunk) do {                                          \
    int kc = (chunk) * 32;                                                    \
    unsigned dbase = sbase + (bufi) * STG_BYTES;                              \
    _Pragma("unroll")                                                         \
    for (int j = 0; j < 4; j++) {                                             \
        int idx = j * 256 + tid;                                              \
        int pl = idx >> 9;                                                    \
        int r  = (idx >> 2) & 127;                                            \
        int sg = idx & 3;                                                     \
        const __half* src = pl == 0                                           \
            ? pA + kc + (size_t)r * lda + sg * 8                              \
            : pB + kc + (size_t)r * ldb + sg * 8;                             \
        cpasync16(dbase + pl * PLANE_BYTES + r * 80 + sg * 16, src);          \
    }                                                                         \
    asm volatile("cp.async.commit_group;" ::: "memory");                      \
} while (0)

    LOAD_STAGE(0, 0);
    LOAD_STAGE(1, 1);     // nch >= 2 for all call sites

    const unsigned aoff = (unsigned)(wm * 64 + (lane & 7) + ((lane >> 3) & 1) * 8) * 80
                        + (unsigned)(lane >> 4) * 16;
    const unsigned boff = (unsigned)(wn * 32 + (lane & 7) + (lane >> 4) * 8) * 80
                        + (unsigned)((lane >> 3) & 1) * 16 + PLANE_BYTES;

    int bufc = 0;
    for (int i = 0; i < nch; i++) {
        if (i + 1 < nch) asm volatile("cp.async.wait_group 1;" ::: "memory");
        else             asm volatile("cp.async.wait_group 0;" ::: "memory");
        __syncthreads();
        if (i + 2 < nch) {
            int lb = bufc + 2; if (lb >= NSTAGE) lb -= NSTAGE;
            LOAD_STAGE(lb, i + 2);
        }
        const unsigned stg = sbase + bufc * STG_BYTES;
#pragma unroll
        for (int ks = 0; ks < 2; ks++) {
            const unsigned ko = ks * 32;
            unsigned bf[2][4];
#pragma unroll
            for (int nt2 = 0; nt2 < 2; nt2++)
                ldmx4(bf[nt2], stg + boff + nt2 * (16 * 80) + ko);
#pragma unroll
            for (int mt = 0; mt < 4; mt++) {
                unsigned ah[4];
                ldmx4(ah, stg + aoff + mt * (16 * 80) + ko);
#pragma unroll
                for (int nt = 0; nt < 4; nt++)
                    mma16816h(acc[mt][nt], ah, &bf[nt >> 1][(nt & 1) * 2]);
            }
        }
        if (++bufc == NSTAGE) bufc = 0;
    }
#undef LOAD_STAGE

    // epilogue
#pragma unroll
    for (int mt = 0; mt < 4; mt++) {
        int m = m0 + wm * 64 + mt * 16 + (lane >> 2);
        float qb0 = bias ? bias[b * INNER + m] : 0.f;
        float qb1 = bias ? bias[b * INNER + m + 8] : 0.f;
#pragma unroll
        for (int nt = 0; nt < 4; nt++) {
            int n = n0 + wn * 32 + nt * 8 + (lane & 3) * 2;
            float v00 = acc[mt][nt][0] + qb0, v01 = acc[mt][nt][1] + qb0;
            float v10 = acc[mt][nt][2] + qb1, v11 = acc[mt][nt][3] + qb1;
            if (ACT == 1) {
                v00 = gelu_exact(v00); v01 = gelu_exact(v01);
                v10 = gelu_exact(v10); v11 = gelu_exact(v11);
            } else if (ACT == 2) {
                v00 = __expf(v00); v01 = __expf(v01);
                v10 = __expf(v10); v11 = __expf(v11);
            }
            size_t i0 = ((size_t)z * strideCz) + (size_t)m * ldc + n;
            size_t i1 = ((size_t)z * strideCz) + (size_t)(m + 8) * ldc + n;
            if (HOUT) {
                __half* Ch = (__half*)Cv;
                __half2 h0; h0.x = __float2half(v00); h0.y = __float2half(v01);
                __half2 h1; h1.x = __float2half(v10); h1.y = __float2half(v11);
                *(__half2*)(Ch + i0) = h0;
                *(__half2*)(Ch + i1) = h1;
            } else if (ACC) {
                float* C = (float*)Cv;
                C[i0] += v00; C[i0 + 1] += v01;
                C[i1] += v10; C[i1 + 1] += v11;
            } else {
                float* C = (float*)Cv;
                float2 f0; f0.x = v00; f0.y = v01;
                float2 f1; f1.x = v10; f1.y = v11;
                *(float2*)(C + i0) = f0;
                *(float2*)(C + i1) = f1;
            }
        }
    }
}

// ------- sumrow: P already holds exp(sim); one read pass for the row sums ------
__global__ __launch_bounds__(256) void sumrow_kernel() {
    int row = blockIdx.x;   // b*512 + hq
    const float4* Pr = (const float4*)(g_Ph + (size_t)row * NX);   // 8 halves per float4
    float* Pl = g_Plat + (size_t)row * NZ;
    float sx = 0.f;
    for (int f = threadIdx.x; f < NX / 8; f += 256) {
        float4 v = Pr[f];
        __half2 h0 = *(__half2*)&v.x, h1 = *(__half2*)&v.y;
        __half2 h2 = *(__half2*)&v.z, h3 = *(__half2*)&v.w;
        float2 f0 = __half22float2(h0), f1 = __half22float2(h1);
        float2 f2 = __half22float2(h2), f3 = __half22float2(h3);
        sx += ((f0.x + f0.y) + (f1.x + f1.y)) + ((f2.x + f2.y) + (f3.x + f3.y));
    }
    float sl = 0.f;
    if (threadIdx.x < NZ) {
        float p = __expf(Pl[threadIdx.x]);   // no max-subtraction (logits ~ ±2)
        Pl[threadIdx.x] = p; sl = p;
    }
    sx = block_red256(sx, 0);
    sl = block_red256(sl, 0);
    if (threadIdx.x == 0) { g_sumPx[row] = sx; g_rowZ[row] = sx + sl; }
}

// ---------------- split-K reduce: AVpart -> AV ----------------
__global__ void av_reduce_kernel() {
    int idx = blockIdx.x * 256 + threadIdx.x;   // < 4*512*768
    int b = idx / (INNER * DD);
    int r = idx - b * (INNER * DD);
    float s = 0.f;
#pragma unroll
    for (int sp = 0; sp < SPLITS; sp++)
        s += g_AVpart[((size_t)(b * SPLITS + sp)) * (INNER * DD) + r];
    g_AV[idx] = s;
}

// ---- combine (tiled per (b,h)): attn = (AV_h@Wvf_h + sumPx*bv + Plat@vlat)/Z -> fp16
__global__ __launch_bounds__(256) void combine_kernel(int l) {
    int blk = blockIdx.x;
    int b = blk >> 3, h = blk & 7;
    __shared__ float As[16][68];      // [k][qi]
    __shared__ float Bs[16][68];      // [k][e]
    __shared__ float Pls[64][65];     // [qi][j]
    __shared__ float Vls[64][65];     // [j][e]
    __shared__ float zr[64], spx[64];
    int tid = threadIdx.x, tx = tid & 15, ty = tid >> 4;

    for (int i = tid; i < 64 * 64; i += 256) {
        int r = i >> 6, c = i & 63;
        Pls[r][c] = g_Plat[((size_t)b * INNER + h * 64 + r) * NZ + c];
        size_t voff = ((size_t)(b * NZ + r)) * QKV_LD + 2 * INNER + h * 64 + c;
        float vv = 0.f;
#pragma unroll
        for (int p = 0; p < QKVSPL; p++) vv += g_qkvpart[p * QKV_PSTR + voff];
        Vls[r][c] = vv;
    }
    if (tid < 64) {
        int r = b * INNER + h * 64 + tid;
        zr[tid] = g_rowZ[r];
        spx[tid] = g_sumPx[r];
    }

    const float* A = g_AV + ((size_t)b * INNER + h * 64) * DD;
    const float* B = g_Wvf + (size_t)l * DD * INNER + h * 64;
    const int lm = tid >> 2, lk = (tid & 3) << 2;
    const int lkr = tid >> 4, ln4 = (tid & 15) << 2;

    float acc[4][4] = {};
    for (int k0 = 0; k0 < DD; k0 += 16) {
        float4 va = *(const float4*)(A + (size_t)lm * DD + k0 + lk);
        As[lk + 0][lm] = va.x; As[lk + 1][lm] = va.y; As[lk + 2][lm] = va.z; As[lk + 3][lm] = va.w;
        float4 vb = *(const float4*)(B + (size_t)(k0 + lkr) * INNER + ln4);
        *(float4*)&Bs[lkr][ln4] = vb;
        __syncthreads();
#pragma unroll
        for (int kk = 0; kk < 16; kk++) {
            float4 a = *(const float4*)&As[kk][ty * 4];
            float4 bv4 = *(const float4*)&Bs[kk][tx * 4];
            float ar[4] = {a.x, a.y, a.z, a.w};
            float br[4] = {bv4.x, bv4.y, bv4.z, bv4.w};
#pragma unroll
            for (int i = 0; i < 4; i++)
#pragma unroll
                for (int j = 0; j < 4; j++) acc[i][j] += ar[i] * br[j];
        }
        __syncthreads();
    }

    for (int jj = 0; jj < NZ; jj++) {
        float pv[4], vv[4];
#pragma unroll
        for (int i = 0; i < 4; i++) pv[i] = Pls[ty * 4 + i][jj];
#pragma unroll
        for (int j = 0; j < 4; j++) vv[j] = Vls[jj][tx * 4 + j];
#pragma unroll
        for (int i = 0; i < 4; i++)
#pragma unroll
            for (int j = 0; j < 4; j++) acc[i][j] += pv[i] * vv[j];
    }

#pragma unroll
    for (int i = 0; i < 4; i++) {
        int qi = ty * 4 + i;
        float invz = 1.0f / zr[qi];
#pragma unroll
        for (int j = 0; j < 4; j++) {
            int e = tx * 4 + j;
            float v = (acc[i][j] + spx[qi] * g_bv[l * INNER + h * 64 + e]) * invz;
            g_attnout_h[((size_t)(b * NZ + qi)) * INNER + h * 64 + e] = __float2half(v);
        }
    }
}

// ---------------- host launch ----------------
static float* symaddrf(const void* sym) {
    void* p = nullptr;
    cudaGetSymbolAddress(&p, sym);
    return (float*)p;
}
static __half* symaddrh(const void* sym) {
    void* p = nullptr;
    cudaGetSymbolAddress(&p, sym);
    return (__half*)p;
}

extern "C" void kernel_launch(void* const* d_in, const int* in_sizes, int n_in,
                              void* d_out, int out_size) {
    const float* x      = (const float*)d_in[0];
    const float* lats   = (const float*)d_in[1];
    const float* femb   = (const float*)d_in[2];
    const float* temb   = (const float*)d_in[3];
    const float* ln_m_g = (const float*)d_in[4];
    const float* ln_m_b = (const float*)d_in[5];
    const float* ln_l_g = (const float*)d_in[6];
    const float* ln_l_b = (const float*)d_in[7];
    const float* Wq     = (const float*)d_in[8];
    const float* Wk     = (const float*)d_in[9];
    const float* Wv     = (const float*)d_in[10];
    const float* Wo     = (const float*)d_in[11];
    const float* ff_g   = (const float*)d_in[12];
    const float* ff_b   = (const float*)d_in[13];
    const float* W1     = (const float*)d_in[14];
    const float* W2     = (const float*)d_in[15];
    const float* out_g  = (const float*)d_in[16];
    const float* out_b  = (const float*)d_in[17];
    float* out = (float*)d_out;

    float* p_lat     = symaddrf(g_lat);
    float* p_qbias   = symaddrf(g_qbias);
    float* p_AVpart  = symaddrf(g_AVpart);
    float* p_W2part  = symaddrf(g_W2part);
    float* p_qkvpart = symaddrf(g_qkvpart);
    __half* p_nxh    = symaddrh(g_nxh);
    __half* p_nxTh   = symaddrh(g_nxTh);
    __half* p_QKh    = symaddrh(g_QKh);
    __half* p_Ph     = symaddrh(g_Ph);
    __half* p_lnlath = symaddrh(g_lnlat_h);
    __half* p_hlnh   = symaddrh(g_hln_h);
    __half* p_atth   = symaddrh(g_attnout_h);
    __half* p_h1h    = symaddrh(g_h1h);
    __half* p_WqkvT  = symaddrh(g_WqkvT);
    __half* p_WoT    = symaddrh(g_WoT);
    __half* p_W1T    = symaddrh(g_W1T);
    __half* p_W2T    = symaddrh(g_W2T);

    static cudaStream_t s2;
    static cudaEvent_t ev1, ev2, ev3;
    static int init_done = 0;
    if (!init_done) {
        cudaFuncSetAttribute(gemm_h_kernel<0, false, false>, cudaFuncAttributeMaxDynamicSharedMemorySize, GEMM_SMEM);
        cudaFuncSetAttribute(gemm_h_kernel<2, false, true >, cudaFuncAttributeMaxDynamicSharedMemorySize, GEMM_SMEM);
        cudaFuncSetAttribute(gemm_h_kernel<1, false, true >, cudaFuncAttributeMaxDynamicSharedMemorySize, GEMM_SMEM);
        cudaStreamCreateWithFlags(&s2, cudaStreamNonBlocking);
        cudaEventCreateWithFlags(&ev1, cudaEventDisableTiming);
        cudaEventCreateWithFlags(&ev2, cudaEventDisableTiming);
        cudaEventCreateWithFlags(&ev3, cudaEventDisableTiming);
        init_done = 1;
    }

    // ---- one-time prep ----
    nx_kernel<<<B4 * NX, 256>>>(x, femb, temb);
    transpose_kernel<<<dim3(NX / 64, DD / 64, B4), 256>>>();
    init_lat_kernel<<<(B4 * NZ * DD) / 256, 256>>>(lats);

    transpose_w_kernel<<<dim3(INNER / 32, DD / 32, LAYERS), 256>>>(
        Wq, p_WqkvT, DD, INNER, 0.125f, (size_t)DD * INNER, (size_t)QKV_LD * DD);
    transpose_w_kernel<<<dim3(INNER / 32, DD / 32, LAYERS), 256>>>(
        Wk, p_WqkvT + (size_t)INNER * DD, DD, INNER, 1.0f, (size_t)DD * INNER, (size_t)QKV_LD * DD);
    transpose_w_kernel<<<dim3(INNER / 32, DD / 32, LAYERS), 256>>>(
        Wv, p_WqkvT + (size_t)2 * INNER * DD, DD, INNER, 1.0f, (size_t)DD * INNER, (size_t)QKV_LD * DD);
    transpose_w_kernel<<<dim3(DD / 32, INNER / 32, LAYERS), 256>>>(
        Wo, p_WoT, INNER, DD, 1.0f, (size_t)INNER * DD, (size_t)INNER * DD);
    transpose_w_kernel<<<dim3(FFH / 32, DD / 32, LAYERS), 256>>>(
        W1, p_W1T, DD, FFH, 1.0f, (size_t)DD * FFH, (size_t)DD * FFH);
    transpose_w_kernel<<<dim3(DD / 32, FFH / 32, LAYERS), 256>>>(
        W2, p_W2T, FFH, DD, 1.0f, (size_t)FFH * DD, (size_t)FFH * DD);
    fold_kernel<<<dim3((DD * INNER) / 256, LAYERS), 256>>>(Wk, Wv, ln_m_g);
    foldbias_kernel<<<dim3(INNER, LAYERS), 256>>>(Wk, Wv, ln_m_b);

    for (int l = 0; l < LAYERS; l++) {
        // latent LN (layers >=1 fold in the previous layer's W2 partials)
        if (l == 0)
            ln768_kernel<true, false><<<B4 * NZ, 256>>>(p_lat, ln_l_g + l * DD, ln_l_b + l * DD, p_lnlath, nullptr);
        else
            ln768_kernel<true, true><<<B4 * NZ, 256>>>(p_lat, ln_l_g + l * DD, ln_l_b + l * DD, p_lnlath, p_lat);

        // fused qkv projection (split-K=4): [256,768] @ [1536,768]^T -> 4 partials
        gemm_h_kernel<0, false, false><<<dim3(2, QKV_LD / 128, QKVSPL), 256, GEMM_SMEM>>>(
            p_lnlath, DD, p_WqkvT + (size_t)l * QKV_LD * DD, DD, p_qkvpart, nullptr,
            DD, QKVSPL, QKV_LD, 0, 0, QKV_PSTR);

        // fork: simlat on s2 (sums partials itself; hidden under qk+GEMM1)
        cudaEventRecord(ev1, 0);
        cudaStreamWaitEvent(s2, ev1, 0);
        simlat_kernel<<<(B4 * INNER * NZ) / 256, 256, 0, s2>>>();

        qk_kernel<<<dim3(DD / 64, HH, B4), 256>>>(l);

        // P = exp(QK @ nx^T + qbias) -> fp16 directly (no max-subtraction)
        gemm_h_kernel<2, false, true><<<dim3(INNER / 128, NX / 128, B4), 256, GEMM_SMEM>>>(
            p_QKh, DD, p_nxh, DD, p_Ph, p_qbias,
            DD, 1, NX, (size_t)INNER * DD, (size_t)NX * DD, (size_t)INNER * NX);

        // fork: sumrow on s2 (in-order after simlat) concurrent with AV gemm
        cudaEventRecord(ev2, 0);
        cudaStreamWaitEvent(s2, ev2, 0);
        sumrow_kernel<<<B4 * INNER, 256, 0, s2>>>();
        cudaEventRecord(ev3, s2);

        // AV = P @ nx (fp16, split-K=14)
        gemm_h_kernel<0, false, false><<<dim3(INNER / 128, DD / 128, B4 * SPLITS), 256, GEMM_SMEM>>>(
            p_Ph, NX, p_nxTh, NX, p_AVpart, nullptr,
            NX, SPLITS, DD, (size_t)INNER * NX, (size_t)DD * NX, (size_t)INNER * DD);

        av_reduce_kernel<<<(B4 * INNER * DD) / 256, 256>>>();

        cudaStreamWaitEvent(0, ev3, 0);
        combine_kernel<<<B4 * HH, 256>>>(l);

        // Wo (split-K=8) -> partials; folded by the FF LN
        gemm_h_kernel<0, false, false><<<dim3(2, DD / 128, W2SPL), 256, GEMM_SMEM>>>(
            p_atth, INNER, p_WoT + (size_t)l * DD * INNER, INNER, p_W2part, nullptr,
            INNER, W2SPL, DD, 0, 0, (size_t)B4 * NZ * DD);

        // FF block: FF LN folds Wo partials + writes lat back; W1 gelu; W2 -> partials
        ln768_kernel<true, true><<<B4 * NZ, 256>>>(p_lat, ff_g + l * DD, ff_b + l * DD, p_hlnh, p_lat);
        gemm_h_kernel<1, false, true><<<dim3(2, FFH / 128, 1), 256, GEMM_SMEM>>>(
            p_hlnh, DD, p_W1T + (size_t)l * FFH * DD, DD, p_h1h, nullptr,
            DD, 1, FFH, 0, 0, 0);
        gemm_h_kernel<0, false, false><<<dim3(2, DD / 128, W2SPL), 256, GEMM_SMEM>>>(
            p_h1h, FFH, p_W2T + (size_t)l * DD * FFH, FFH, p_W2part, nullptr,
            FFH, W2SPL, DD, 0, 0, (size_t)B4 * NZ * DD);
    }

    // final LN folds the last layer's W2 partials
    ln768_kernel<false, true><<<B4 * NZ, 256>>>(p_lat, out_g, out_b, out, p_lat);
}

// round 16
// speedup vs baseline: 1.0284x; 1.0284x over previous
#include <cuda_runtime.h>
#include <cuda_fp16.h>
#include <math.h>

#define B4     4
#define FFRAMES 16
#define VV     196
#define DD     768
#define NX     25088          // T*F*V
#define NZ     64
#define HH     8
#define INNER  512
#define QKV_LD 1536           // 3*INNER
#define FFH    3072
#define LAYERS 6
#define SPLITS 14             // split-K for AV gemm (784/14 = 56 chunks)
#define W2SPL  8              // split-K for Wo / W2 gemms
#define QKVSPL 3              // split-K for qkv gemm

// ---------------- scratch (static device memory; no allocations) ----------------
__device__ __align__(256) __half g_nxh[(size_t)B4 * NX * DD];        // fp16 normalized x
__device__ __align__(256) __half g_nxTh[(size_t)B4 * DD * NX];       // transposed
__device__ __align__(256) __half g_Ph[(size_t)B4 * INNER * NX];      // exp(sim) fp16 (GEMM1 epilogue)
__device__ __align__(256) __half g_QKh[B4 * INNER * DD];             // QK fp16
__device__ float g_Plat[B4 * INNER * NZ];
__device__ float g_qbias[B4 * INNER];
__device__ float g_rowZ[B4 * INNER];
__device__ float g_sumPx[B4 * INNER];
__device__ __align__(256) float g_AVpart[(size_t)B4 * SPLITS * INNER * DD];
__device__ __align__(256) float g_AV[B4 * INNER * DD];
__device__ __align__(256) float g_qkv[B4 * NZ * QKV_LD];             // fused q|k|v
__device__ __align__(256) float g_qkvpart[(size_t)QKVSPL * B4 * NZ * QKV_LD];
__device__ __align__(256) float g_W2part[(size_t)W2SPL * B4 * NZ * DD];  // Wo & W2 partials (time-shared)
__device__ float g_Wkf[LAYERS * DD * INNER];
__device__ float g_Wvf[LAYERS * DD * INNER];
__device__ float g_bk[LAYERS * INNER];
__device__ float g_bv[LAYERS * INNER];
__device__ float g_lat[B4 * NZ * DD];
// fp16 operands for small tensor GEMMs (all layers precomputed)
__device__ __align__(256) __half g_lnlat_h[B4 * NZ * DD];
__device__ __align__(256) __half g_hln_h[B4 * NZ * DD];
__device__ __align__(256) __half g_attnout_h[B4 * NZ * INNER];
__device__ __align__(256) __half g_h1h[B4 * NZ * FFH];
__device__ __align__(256) __half g_WqkvT[(size_t)LAYERS * QKV_LD * DD];
__device__ __align__(256) __half g_WoT[(size_t)LAYERS * DD * INNER];
__device__ __align__(256) __half g_W1T[(size_t)LAYERS * FFH * DD];
__device__ __align__(256) __half g_W2T[(size_t)LAYERS * DD * FFH];

// ---------------- PTX helpers ----------------
__device__ __forceinline__ unsigned smem_u32(const void* p) {
    unsigned a;
    asm("{ .reg .u64 t; cvta.to.shared.u64 t, %1; cvt.u32.u64 %0, t; }" : "=r"(a) : "l"(p));
    return a;
}
__device__ __forceinline__ void cpasync16(unsigned dst, const void* src) {
    asm volatile("cp.async.cg.shared.global [%0], [%1], 16;" :: "r"(dst), "l"(src) : "memory");
}
__device__ __forceinline__ void mma16816h(float* c, const unsigned* a, const unsigned* b) {
    asm volatile(
        "mma.sync.aligned.m16n8k16.row.col.f32.f16.f16.f32 "
        "{%0,%1,%2,%3}, {%4,%5,%6,%7}, {%8,%9}, {%0,%1,%2,%3};"
        : "+f"(c[0]), "+f"(c[1]), "+f"(c[2]), "+f"(c[3])
        : "r"(a[0]), "r"(a[1]), "r"(a[2]), "r"(a[3]), "r"(b[0]), "r"(b[1]));
}
__device__ __forceinline__ void ldmx4(unsigned* r, unsigned addr) {
    asm volatile("ldmatrix.sync.aligned.m8n8.x4.shared.b16 {%0,%1,%2,%3}, [%4];"
        : "=r"(r[0]), "=r"(r[1]), "=r"(r[2]), "=r"(r[3]) : "r"(addr));
}

// ---------------- reductions / misc ----------------
__device__ __forceinline__ float block_red256(float v, int is_max) {
    __shared__ float sm[8];
    int lane = threadIdx.x & 31, w = threadIdx.x >> 5;
#pragma unroll
    for (int o = 16; o; o >>= 1) {
        float t = __shfl_xor_sync(0xffffffffu, v, o);
        v = is_max ? fmaxf(v, t) : v + t;
    }
    __syncthreads();
    if (lane == 0) sm[w] = v;
    __syncthreads();
    if (w == 0) {
        v = sm[lane & 7];
#pragma unroll
        for (int o = 4; o; o >>= 1) {
            float t = __shfl_xor_sync(0xffffffffu, v, o);
            v = is_max ? fmaxf(v, t) : v + t;
        }
        if (lane == 0) sm[0] = v;
    }
    __syncthreads();
    return sm[0];
}

__device__ __forceinline__ float gelu_exact(float x) {
    return 0.5f * x * (1.0f + erff(x * 0.7071067811865476f));
}

// ---------------- nx: embeds + LN(no affine) -> fp16 ----------------
__global__ __launch_bounds__(256) void nx_kernel(const float* __restrict__ x,
                                                 const float* __restrict__ femb,
                                                 const float* __restrict__ temb) {
    int row = blockIdx.x;                // b*NX + n
    int n = row % NX;
    int t = n / (FFRAMES * VV);
    int f = (n / VV) % FFRAMES;
    const float* xr = x + (size_t)row * DD;
    float vals[3], s = 0.f;
#pragma unroll
    for (int i = 0; i < 3; i++) {
        int d = threadIdx.x + i * 256;
        float v = xr[d] + femb[f * DD + d] + temb[t * DD + d];
        vals[i] = v; s += v;
    }
    float mean = block_red256(s, 0) * (1.0f / DD);
    float q = 0.f;
#pragma unroll
    for (int i = 0; i < 3; i++) { float dv = vals[i] - mean; q += dv * dv; }
    float var = block_red256(q, 0) * (1.0f / DD);
    float r = rsqrtf(var + 1e-5f);
    __half* o = g_nxh + (size_t)row * DD;
#pragma unroll
    for (int i = 0; i < 3; i++) {
        int d = threadIdx.x + i * 256;
        o[d] = __float2half((vals[i] - mean) * r);
    }
}

// ---------------- tiled transpose: g_nxh -> g_nxTh ----------------
__global__ __launch_bounds__(256) void transpose_kernel() {
    __shared__ __half th[64][66];
    int tok0 = blockIdx.x * 64, d0 = blockIdx.y * 64, b = blockIdx.z;
    const __half* in = g_nxh + (size_t)b * NX * DD;
#pragma unroll
    for (int i = 0; i < 8; i++) {
        int idx = i * 256 + threadIdx.x;
        int r = idx >> 5, c2 = idx & 31;
        __half2 vh = *((const __half2*)(in + (size_t)(tok0 + r) * DD + d0) + c2);
        th[r][c2 * 2] = vh.x; th[r][c2 * 2 + 1] = vh.y;
    }
    __syncthreads();
    __half* out = g_nxTh + (size_t)b * DD * NX;
#pragma unroll
    for (int i = 0; i < 8; i++) {
        int idx = i * 256 + threadIdx.x;
        int r = idx >> 5, c2 = idx & 31;      // r = d row, c2 = tok pair
        __half2 vh; vh.x = th[c2 * 2][r]; vh.y = th[c2 * 2 + 1][r];
        *((__half2*)(out + (size_t)(d0 + r) * NX + tok0) + c2) = vh;
    }
}

// -------- weight transpose+convert: in[K,N] fp32 -> out[N,K] fp16 * scale; z = layer ----
__global__ __launch_bounds__(256) void transpose_w_kernel(const float* __restrict__ in,
                                                          __half* __restrict__ out,
                                                          int K, int N, float scale,
                                                          size_t inLS, size_t outLS) {
    __shared__ __half t[32][33];
    int n0 = blockIdx.x * 32, k0 = blockIdx.y * 32;
    in  += (size_t)blockIdx.z * inLS;
    out += (size_t)blockIdx.z * outLS;
    int tid = threadIdx.x;
#pragma unroll
    for (int i = 0; i < 4; i++) {
        int idx = i * 256 + tid;
        int r = idx >> 5, c = idx & 31;     // r = k-local, c = n-local
        t[r][c] = __float2half(in[(size_t)(k0 + r) * N + n0 + c] * scale);
    }
    __syncthreads();
#pragma unroll
    for (int i = 0; i < 4; i++) {
        int idx = i * 256 + tid;
        int r = idx >> 5, c = idx & 31;     // r = n-local, c = k-local
        out[(size_t)(n0 + r) * K + k0 + c] = t[c][r];
    }
}

// ------ LN over 768 with affine; fp32/fp16 output; optional partial add-back ------
// ADDP: in-value = in[row] + sum of W2SPL partial planes (g_W2part); writes the
// summed residual back to latwb so later consumers see the full value.
template <bool HOUT, bool ADDP>
__global__ __launch_bounds__(256) void ln768_kernel(const float* __restrict__ in,
                                                    const float* __restrict__ gg,
                                                    const float* __restrict__ bb,
                                                    void* __restrict__ outv,
                                                    float* __restrict__ latwb) {
    int row = blockIdx.x;
    const float* xr = in + (size_t)row * DD;
    float vals[3], s = 0.f;
#pragma unroll
    for (int i = 0; i < 3; i++) {
        int d = threadIdx.x + i * 256;
        float v = xr[d];
        if (ADDP) {
#pragma unroll
            for (int p = 0; p < W2SPL; p++)
                v += g_W2part[(size_t)p * (B4 * NZ * DD) + (size_t)row * DD + d];
        }
        vals[i] = v; s += v;
    }
    if (ADDP) {
#pragma unroll
        for (int i = 0; i < 3; i++) {
            int d = threadIdx.x + i * 256;
            latwb[(size_t)row * DD + d] = vals[i];
        }
    }
    float mean = block_red256(s, 0) * (1.0f / DD);
    float q = 0.f;
#pragma unroll
    for (int i = 0; i < 3; i++) { float dv = vals[i] - mean; q += dv * dv; }
    float var = block_red256(q, 0) * (1.0f / DD);
    float r = rsqrtf(var + 1e-5f);
#pragma unroll
    for (int i = 0; i < 3; i++) {
        int d = threadIdx.x + i * 256;
        float v = (vals[i] - mean) * r * gg[d] + bb[d];
        if (HOUT) ((__half*)outv)[(size_t)row * DD + d] = __float2half(v);
        else      ((float*)outv)[(size_t)row * DD + d] = v;
    }
}

__global__ void init_lat_kernel(const float* __restrict__ lat) {
    int idx = blockIdx.x * 256 + threadIdx.x;
    g_lat[idx] = lat[idx % (NZ * DD)];
}

// ---------------- fold LN(media) gamma/beta into Wk/Wv (all layers) ----------------
__global__ void fold_kernel(const float* __restrict__ Wk, const float* __restrict__ Wv,
                            const float* __restrict__ gm) {
    int l = blockIdx.y;
    int idx = blockIdx.x * 256 + threadIdx.x;   // < 768*512
    int d = idx >> 9;
    float g = gm[l * DD + d];
    size_t off = (size_t)l * DD * INNER + idx;
    g_Wkf[off] = g * Wk[off];
    g_Wvf[off] = g * Wv[off];
}

__global__ __launch_bounds__(256) void foldbias_kernel(const float* __restrict__ Wk,
                                                       const float* __restrict__ Wv,
                                                       const float* __restrict__ bm) {
    int e = blockIdx.x, l = blockIdx.y;
    float sk = 0.f, sv = 0.f;
    for (int d = threadIdx.x; d < DD; d += 256) {
        float bb = bm[l * DD + d];
        size_t off = (size_t)l * DD * INNER + (size_t)d * INNER + e;
        sk += bb * Wk[off];
        sv += bb * Wv[off];
    }
    sk = block_red256(sk, 0);
    sv = block_red256(sv, 0);
    if (threadIdx.x == 0) { g_bk[l * INNER + e] = sk; g_bv[l * INNER + e] = sv; }
}

// ---------------- qkv split-K reduce ----------------
__global__ void qkv_reduce_kernel() {
    int idx = blockIdx.x * 256 + threadIdx.x;   // < 256*1536
    float s = 0.f;
#pragma unroll
    for (int p = 0; p < QKVSPL; p++)
        s += g_qkvpart[(size_t)p * (B4 * NZ * QKV_LD) + idx];
    g_qkv[idx] = s;
}

// ---------------- QK (reassociated q@Wkf) -> fp16; d0==0 blocks also do qbias ----
__global__ __launch_bounds__(256) void qk_kernel(int l) {
    int d0 = blockIdx.x * 64;
    int h = blockIdx.y;
    int b = blockIdx.z;
    __shared__ float qs[64][65];
    __shared__ float ws[64][65];
    int tid = threadIdx.x;
    const float* Wkf = g_Wkf + (size_t)l * DD * INNER;
#pragma unroll
    for (int i = 0; i < 16; i++) {
        int idx = tid + i * 256;
        int r = idx >> 6, c = idx & 63;
        qs[r][c] = g_qkv[(size_t)(b * NZ + r) * QKV_LD + h * 64 + c];
        ws[r][c] = Wkf[(size_t)(d0 + r) * INNER + h * 64 + c];
    }
    __syncthreads();
    if (blockIdx.x == 0 && tid < 64) {
        const float* bkp = g_bk + l * INNER + h * 64;
        float qb = 0.f;
#pragma unroll 8
        for (int dh = 0; dh < 64; dh++) qb += qs[tid][dh] * bkp[dh];
        g_qbias[b * INNER + h * 64 + tid] = qb;
    }
    int dl = tid & 63;
    int qg = tid >> 6;
    float acc[16] = {};
    for (int dh = 0; dh < 64; dh++) {
        float w = ws[dl][dh];
#pragma unroll
        for (int i = 0; i < 16; i++) acc[i] += qs[qg * 16 + i][dh] * w;
    }
#pragma unroll
    for (int i = 0; i < 16; i++) {
        int qi = qg * 16 + i;
        g_QKh[((size_t)b * INNER + h * 64 + qi) * DD + d0 + dl] = __float2half(acc[i]);
    }
}

// ---- simlat (latent-key scores only; runs on side stream) ----
__global__ void simlat_kernel() {
    int t = blockIdx.x * 256 + threadIdx.x;
    int j = t & 63; int row = t >> 6;
    int b = row >> 9, hq = row & 511, h = hq >> 6, qi = hq & 63;
    const float* qr = g_qkv + (size_t)(b * NZ + qi) * QKV_LD + h * 64;
    const float* kr = g_qkv + (size_t)(b * NZ + j) * QKV_LD + INNER + h * 64;
    float s = 0.f;
#pragma unroll 8
    for (int dh = 0; dh < 64; dh++) s += qr[dh] * kr[dh];
    g_Plat[t] = s;
}

// ================= fp16 GEMM via mma.sync + ldmatrix (3-stage pipeline) =======
// ACT: 0 = none, 1 = gelu, 2 = exp (no max-subtraction softmax numerator)
#define PLANE_BYTES 10240
#define STG_BYTES   (2 * PLANE_BYTES)
#define NSTAGE      3
#define GEMM_SMEM   (NSTAGE * STG_BYTES)

template <int ACT, bool ACC, bool HOUT>
__global__ __launch_bounds__(256, 2) void gemm_h_kernel(
    const __half* __restrict__ A, int lda,
    const __half* __restrict__ B, int ldb,
    void* __restrict__ Cv, const float* __restrict__ bias,
    int kTotal, int nsplit, int ldc,
    size_t strideAz, size_t strideBz, size_t strideCz)
{
    extern __shared__ char smem[];
    const unsigned sbase = smem_u32(smem);
    const int tid = threadIdx.x;
    const int lane = tid & 31, w = tid >> 5;
    const int wm = w & 1, wn = w >> 1;
    const int m0 = blockIdx.x * 128, n0 = blockIdx.y * 128;
    const int z = blockIdx.z, b = z / nsplit, s = z % nsplit;
    const int kbeg = s * (kTotal / nsplit);
    const int nch = kTotal / (32 * nsplit);
    const __half* pA = A + (size_t)b * strideAz + (size_t)m0 * lda + kbeg;
    const __half* pB = B + (size_t)b * strideBz + (size_t)n0 * ldb + kbeg;

    float acc[4][4][4];
#pragma unroll
    for (int i = 0; i < 4; i++)
#pragma unroll
        for (int j = 0; j < 4; j++)
#pragma unroll
            for (int k = 0; k < 4; k++) acc[i][j][k] = 0.f;

#define LOAD_STAGE(bufi, chunk) do {                                          \
    int kc = (chunk) * 32;                                                    \
    unsigned dbase = sbase + (bufi) * STG_BYTES;                              \
    _Pragma("unroll")                                                         \
    for (int j = 0; j < 4; j++) {                                             \
        int idx = j * 256 + tid;                                              \
        int pl = idx >> 9;                                                    \
        int r  = (idx >> 2) & 127;                                            \
        int sg = idx & 3;                                                     \
        const __half* src = pl == 0                                           \
            ? pA + kc + (size_t)r * lda + sg * 8                              \
            : pB + kc + (size_t)r * ldb + sg * 8;                             \
        cpasync16(dbase + pl * PLANE_BYTES + r * 80 + sg * 16, src);          \
    }                                                                         \
    asm volatile("cp.async.commit_group;" ::: "memory");                      \
} while (0)

    LOAD_STAGE(0, 0);
    LOAD_STAGE(1, 1);     // nch >= 2 for all call sites

    const unsigned aoff = (unsigned)(wm * 64 + (lane & 7) + ((lane >> 3) & 1) * 8) * 80
                        + (unsigned)(lane >> 4) * 16;
    const unsigned boff = (unsigned)(wn * 32 + (lane & 7) + (lane >> 4) * 8) * 80
                        + (unsigned)((lane >> 3) & 1) * 16 + PLANE_BYTES;

    int bufc = 0;
    for (int i = 0; i < nch; i++) {
        if (i + 1 < nch) asm volatile("cp.async.wait_group 1;" ::: "memory");
        else             asm volatile("cp.async.wait_group 0;" ::: "memory");
        __syncthreads();
        if (i + 2 < nch) {
            int lb = bufc + 2; if (lb >= NSTAGE) lb -= NSTAGE;
            LOAD_STAGE(lb, i + 2);
        }
        const unsigned stg = sbase + bufc * STG_BYTES;
#pragma unroll
        for (int ks = 0; ks < 2; ks++) {
            const unsigned ko = ks * 32;
            unsigned bf[2][4];
#pragma unroll
            for (int nt2 = 0; nt2 < 2; nt2++)
                ldmx4(bf[nt2], stg + boff + nt2 * (16 * 80) + ko);
#pragma unroll
            for (int mt = 0; mt < 4; mt++) {
                unsigned ah[4];
                ldmx4(ah, stg + aoff + mt * (16 * 80) + ko);
#pragma unroll
                for (int nt = 0; nt < 4; nt++)
                    mma16816h(acc[mt][nt], ah, &bf[nt >> 1][(nt & 1) * 2]);
            }
        }
        if (++bufc == NSTAGE) bufc = 0;
    }
#undef LOAD_STAGE

    // epilogue
#pragma unroll
    for (int mt = 0; mt < 4; mt++) {
        int m = m0 + wm * 64 + mt * 16 + (lane >> 2);
        float qb0 = bias ? bias[b * INNER + m] : 0.f;
        float qb1 = bias ? bias[b * INNER + m + 8] : 0.f;
#pragma unroll
        for (int nt = 0; nt < 4; nt++) {
            int n = n0 + wn * 32 + nt * 8 + (lane & 3) * 2;
            float v00 = acc[mt][nt][0] + qb0, v01 = acc[mt][nt][1] + qb0;
            float v10 = acc[mt][nt][2] + qb1, v11 = acc[mt][nt][3] + qb1;
            if (ACT == 1) {
                v00 = gelu_exact(v00); v01 = gelu_exact(v01);
                v10 = gelu_exact(v10); v11 = gelu_exact(v11);
            } else if (ACT == 2) {
                v00 = __expf(v00); v01 = __expf(v01);
                v10 = __expf(v10); v11 = __expf(v11);
            }
            size_t i0 = ((size_t)z * strideCz) + (size_t)m * ldc + n;
            size_t i1 = ((size_t)z * strideCz) + (size_t)(m + 8) * ldc + n;
            if (HOUT) {
                __half* Ch = (__half*)Cv;
                __half2 h0; h0.x = __float2half(v00); h0.y = __float2half(v01);
                __half2 h1; h1.x = __float2half(v10); h1.y = __float2half(v11);
                *(__half2*)(Ch + i0) = h0;
                *(__half2*)(Ch + i1) = h1;
            } else if (ACC) {
                float* C = (float*)Cv;
                C[i0] += v00; C[i0 + 1] += v01;
                C[i1] += v10; C[i1 + 1] += v11;
            } else {
                float* C = (float*)Cv;
                float2 f0; f0.x = v00; f0.y = v01;
                float2 f1; f1.x = v10; f1.y = v11;
                *(float2*)(C + i0) = f0;
                *(float2*)(C + i1) = f1;
            }
        }
    }
}

// ------- sumrow: P already holds exp(sim); one read pass for the row sums ------
__global__ __launch_bounds__(256) void sumrow_kernel() {
    int row = blockIdx.x;   // b*512 + hq
    const float4* Pr = (const float4*)(g_Ph + (size_t)row * NX);   // 8 halves per float4
    float* Pl = g_Plat + (size_t)row * NZ;
    float sx = 0.f;
    for (int f = threadIdx.x; f < NX / 8; f += 256) {
        float4 v = Pr[f];
        __half2 h0 = *(__half2*)&v.x, h1 = *(__half2*)&v.y;
        __half2 h2 = *(__half2*)&v.z, h3 = *(__half2*)&v.w;
        float2 f0 = __half22float2(h0), f1 = __half22float2(h1);
        float2 f2 = __half22float2(h2), f3 = __half22float2(h3);
        sx += ((f0.x + f0.y) + (f1.x + f1.y)) + ((f2.x + f2.y) + (f3.x + f3.y));
    }
    float sl = 0.f;
    if (threadIdx.x < NZ) {
        float p = __expf(Pl[threadIdx.x]);   // no max-subtraction (logits ~ ±2)
        Pl[threadIdx.x] = p; sl = p;
    }
    sx = block_red256(sx, 0);
    sl = block_red256(sl, 0);
    if (threadIdx.x == 0) { g_sumPx[row] = sx; g_rowZ[row] = sx + sl; }
}

// ---------------- split-K reduce: AVpart -> AV ----------------
__global__ void av_reduce_kernel() {
    int idx = blockIdx.x * 256 + threadIdx.x;   // < 4*512*768
    int b = idx / (INNER * DD);
    int r = idx - b * (INNER * DD);
    float s = 0.f;
#pragma unroll
    for (int sp = 0; sp < SPLITS; sp++)
        s += g_AVpart[((size_t)(b * SPLITS + sp)) * (INNER * DD) + r];
    g_AV[idx] = s;
}

// ---- combine (tiled per (b,h)): attn = (AV_h@Wvf_h + sumPx*bv + Plat@vlat)/Z -> fp16
__global__ __launch_bounds__(256) void combine_kernel(int l) {
    int blk = blockIdx.x;
    int b = blk >> 3, h = blk & 7;
    __shared__ float As[16][68];      // [k][qi]
    __shared__ float Bs[16][68];      // [k][e]
    __shared__ float Pls[64][65];     // [qi][j]
    __shared__ float Vls[64][65];     // [j][e]
    __shared__ float zr[64], spx[64];
    int tid = threadIdx.x, tx = tid & 15, ty = tid >> 4;

    for (int i = tid; i < 64 * 64; i += 256) {
        int r = i >> 6, c = i & 63;
        Pls[r][c] = g_Plat[((size_t)b * INNER + h * 64 + r) * NZ + c];
        Vls[r][c] = g_qkv[((size_t)(b * NZ + r)) * QKV_LD + 2 * INNER + h * 64 + c];
    }
    if (tid < 64) {
        int r = b * INNER + h * 64 + tid;
        zr[tid] = g_rowZ[r];
        spx[tid] = g_sumPx[r];
    }

    const float* A = g_AV + ((size_t)b * INNER + h * 64) * DD;
    const float* B = g_Wvf + (size_t)l * DD * INNER + h * 64;
    const int lm = tid >> 2, lk = (tid & 3) << 2;
    const int lkr = tid >> 4, ln4 = (tid & 15) << 2;

    float acc[4][4] = {};
    for (int k0 = 0; k0 < DD; k0 += 16) {
        float4 va = *(const float4*)(A + (size_t)lm * DD + k0 + lk);
        As[lk + 0][lm] = va.x; As[lk + 1][lm] = va.y; As[lk + 2][lm] = va.z; As[lk + 3][lm] = va.w;
        float4 vb = *(const float4*)(B + (size_t)(k0 + lkr) * INNER + ln4);
        *(float4*)&Bs[lkr][ln4] = vb;
        __syncthreads();
#pragma unroll
        for (int kk = 0; kk < 16; kk++) {
            float4 a = *(const float4*)&As[kk][ty * 4];
            float4 bv4 = *(const float4*)&Bs[kk][tx * 4];
            float ar[4] = {a.x, a.y, a.z, a.w};
            float br[4] = {bv4.x, bv4.y, bv4.z, bv4.w};
#pragma unroll
            for (int i = 0; i < 4; i++)
#pragma unroll
                for (int j = 0; j < 4; j++) acc[i][j] += ar[i] * br[j];
        }
        __syncthreads();
    }

    for (int jj = 0; jj < NZ; jj++) {
        float pv[4], vv[4];
#pragma unroll
        for (int i = 0; i < 4; i++) pv[i] = Pls[ty * 4 + i][jj];
#pragma unroll
        for (int j = 0; j < 4; j++) vv[j] = Vls[jj][tx * 4 + j];
#pragma unroll
        for (int i = 0; i < 4; i++)
#pragma unroll
            for (int j = 0; j < 4; j++) acc[i][j] += pv[i] * vv[j];
    }

#pragma unroll
    for (int i = 0; i < 4; i++) {
        int qi = ty * 4 + i;
        float invz = 1.0f / zr[qi];
#pragma unroll
        for (int j = 0; j < 4; j++) {
            int e = tx * 4 + j;
            float v = (acc[i][j] + spx[qi] * g_bv[l * INNER + h * 64 + e]) * invz;
            g_attnout_h[((size_t)(b * NZ + qi)) * INNER + h * 64 + e] = __float2half(v);
        }
    }
}

// ---------------- host launch ----------------
static float* symaddrf(const void* sym) {
    void* p = nullptr;
    cudaGetSymbolAddress(&p, sym);
    return (float*)p;
}
static __half* symaddrh(const void* sym) {
    void* p = nullptr;
    cudaGetSymbolAddress(&p, sym);
    return (__half*)p;
}

extern "C" void kernel_launch(void* const* d_in, const int* in_sizes, int n_in,
                              void* d_out, int out_size) {
    const float* x      = (const float*)d_in[0];
    const float* lats   = (const float*)d_in[1];
    const float* femb   = (const float*)d_in[2];
    const float* temb   = (const float*)d_in[3];
    const float* ln_m_g = (const float*)d_in[4];
    const float* ln_m_b = (const float*)d_in[5];
    const float* ln_l_g = (const float*)d_in[6];
    const float* ln_l_b = (const float*)d_in[7];
    const float* Wq     = (const float*)d_in[8];
    const float* Wk     = (const float*)d_in[9];
    const float* Wv     = (const float*)d_in[10];
    const float* Wo     = (const float*)d_in[11];
    const float* ff_g   = (const float*)d_in[12];
    const float* ff_b   = (const float*)d_in[13];
    const float* W1     = (const float*)d_in[14];
    const float* W2     = (const float*)d_in[15];
    const float* out_g  = (const float*)d_in[16];
    const float* out_b  = (const float*)d_in[17];
    float* out = (float*)d_out;

    float* p_lat     = symaddrf(g_lat);
    float* p_qbias   = symaddrf(g_qbias);
    float* p_AVpart  = symaddrf(g_AVpart);
    float* p_W2part  = symaddrf(g_W2part);
    float* p_qkvpart = symaddrf(g_qkvpart);
    __half* p_nxh    = symaddrh(g_nxh);
    __half* p_nxTh   = symaddrh(g_nxTh);
    __half* p_QKh    = symaddrh(g_QKh);
    __half* p_Ph     = symaddrh(g_Ph);
    __half* p_lnlath = symaddrh(g_lnlat_h);
    __half* p_hlnh   = symaddrh(g_hln_h);
    __half* p_atth   = symaddrh(g_attnout_h);
    __half* p_h1h    = symaddrh(g_h1h);
    __half* p_WqkvT  = symaddrh(g_WqkvT);
    __half* p_WoT    = symaddrh(g_WoT);
    __half* p_W1T    = symaddrh(g_W1T);
    __half* p_W2T    = symaddrh(g_W2T);

    static cudaStream_t s2;
    static cudaEvent_t ev1, ev2, ev3;
    static int init_done = 0;
    if (!init_done) {
        cudaFuncSetAttribute(gemm_h_kernel<0, false, false>, cudaFuncAttributeMaxDynamicSharedMemorySize, GEMM_SMEM);
        cudaFuncSetAttribute(gemm_h_kernel<2, false, true >, cudaFuncAttributeMaxDynamicSharedMemorySize, GEMM_SMEM);
        cudaFuncSetAttribute(gemm_h_kernel<1, false, true >, cudaFuncAttributeMaxDynamicSharedMemorySize, GEMM_SMEM);
        cudaStreamCreateWithFlags(&s2, cudaStreamNonBlocking);
        cudaEventCreateWithFlags(&ev1, cudaEventDisableTiming);
        cudaEventCreateWithFlags(&ev2, cudaEventDisableTiming);
        cudaEventCreateWithFlags(&ev3, cudaEventDisableTiming);
        init_done = 1;
    }

    // ---- one-time prep ----
    nx_kernel<<<B4 * NX, 256>>>(x, femb, temb);
    transpose_kernel<<<dim3(NX / 64, DD / 64, B4), 256>>>();
    init_lat_kernel<<<(B4 * NZ * DD) / 256, 256>>>(lats);

    transpose_w_kernel<<<dim3(INNER / 32, DD / 32, LAYERS), 256>>>(
        Wq, p_WqkvT, DD, INNER, 0.125f, (size_t)DD * INNER, (size_t)QKV_LD * DD);
    transpose_w_kernel<<<dim3(INNER / 32, DD / 32, LAYERS), 256>>>(
        Wk, p_WqkvT + (size_t)INNER * DD, DD, INNER, 1.0f, (size_t)DD * INNER, (size_t)QKV_LD * DD);
    transpose_w_kernel<<<dim3(INNER / 32, DD / 32, LAYERS), 256>>>(
        Wv, p_WqkvT + (size_t)2 * INNER * DD, DD, INNER, 1.0f, (size_t)DD * INNER, (size_t)QKV_LD * DD);
    transpose_w_kernel<<<dim3(DD / 32, INNER / 32, LAYERS), 256>>>(
        Wo, p_WoT, INNER, DD, 1.0f, (size_t)INNER * DD, (size_t)INNER * DD);
    transpose_w_kernel<<<dim3(FFH / 32, DD / 32, LAYERS), 256>>>(
        W1, p_W1T, DD, FFH, 1.0f, (size_t)DD * FFH, (size_t)DD * FFH);
    transpose_w_kernel<<<dim3(DD / 32, FFH / 32, LAYERS), 256>>>(
        W2, p_W2T, FFH, DD, 1.0f, (size_t)FFH * DD, (size_t)FFH * DD);
    fold_kernel<<<dim3((DD * INNER) / 256, LAYERS), 256>>>(Wk, Wv, ln_m_g);
    foldbias_kernel<<<dim3(INNER, LAYERS), 256>>>(Wk, Wv, ln_m_b);

    for (int l = 0; l < LAYERS; l++) {
        // latent LN (layers >=1 fold in the previous layer's W2 partials)
        if (l == 0)
            ln768_kernel<true, false><<<B4 * NZ, 256>>>(p_lat, ln_l_g + l * DD, ln_l_b + l * DD, p_lnlath, nullptr);
        else
            ln768_kernel<true, true><<<B4 * NZ, 256>>>(p_lat, ln_l_g + l * DD, ln_l_b + l * DD, p_lnlath, p_lat);

        // fused qkv projection (split-K=3): [256,768] @ [1536,768]^T -> 3 partials
        gemm_h_kernel<0, false, false><<<dim3(2, QKV_LD / 128, QKVSPL), 256, GEMM_SMEM>>>(
            p_lnlath, DD, p_WqkvT + (size_t)l * QKV_LD * DD, DD, p_qkvpart, nullptr,
            DD, QKVSPL, QKV_LD, 0, 0, (size_t)B4 * NZ * QKV_LD);
        qkv_reduce_kernel<<<(B4 * NZ * QKV_LD) / 256, 256>>>();

        // fork: simlat on s2 (only combine needs it)
        cudaEventRecord(ev1, 0);
        cudaStreamWaitEvent(s2, ev1, 0);
        simlat_kernel<<<(B4 * INNER * NZ) / 256, 256, 0, s2>>>();

        qk_kernel<<<dim3(DD / 64, HH, B4), 256>>>(l);

        // P = exp(QK @ nx^T + qbias) -> fp16 directly (no max-subtraction)
        gemm_h_kernel<2, false, true><<<dim3(INNER / 128, NX / 128, B4), 256, GEMM_SMEM>>>(
            p_QKh, DD, p_nxh, DD, p_Ph, p_qbias,
            DD, 1, NX, (size_t)INNER * DD, (size_t)NX * DD, (size_t)INNER * NX);

        // fork: sumrow on s2 (in-order after simlat) concurrent with AV gemm
        cudaEventRecord(ev2, 0);
        cudaStreamWaitEvent(s2, ev2, 0);
        sumrow_kernel<<<B4 * INNER, 256, 0, s2>>>();
        cudaEventRecord(ev3, s2);

        // AV = P @ nx (fp16, split-K=14)
        gemm_h_kernel<0, false, false><<<dim3(INNER / 128, DD / 128, B4 * SPLITS), 256, GEMM_SMEM>>>(
            p_Ph, NX, p_nxTh, NX, p_AVpart, nullptr,
            NX, SPLITS, DD, (size_t)INNER * NX, (size_t)DD * NX, (size_t)INNER * DD);

        av_reduce_kernel<<<(B4 * INNER * DD) / 256, 256>>>();

        cudaStreamWaitEvent(0, ev3, 0);
        combine_kernel<<<B4 * HH, 256>>>(l);

        // Wo (split-K=8) -> partials; folded by the FF LN
        gemm_h_kernel<0, false, false><<<dim3(2, DD / 128, W2SPL), 256, GEMM_SMEM>>>(
            p_atth, INNER, p_WoT + (size_t)l * DD * INNER, INNER, p_W2part, nullptr,
            INNER, W2SPL, DD, 0, 0, (size_t)B4 * NZ * DD);

        // FF block: FF LN folds Wo partials + writes lat back; W1 gelu; W2 -> partials
        ln768_kernel<true, true><<<B4 * NZ, 256>>>(p_lat, ff_g + l * DD, ff_b + l * DD, p_hlnh, p_lat);
        gemm_h_kernel<1, false, true><<<dim3(2, FFH / 128, 1), 256, GEMM_SMEM>>>(
            p_hlnh, DD, p_W1T + (size_t)l * FFH * DD, DD, p_h1h, nullptr,
            DD, 1, FFH, 0, 0, 0);
        gemm_h_kernel<0, false, false><<<dim3(2, DD / 128, W2SPL), 256, GEMM_SMEM>>>(
            p_h1h, FFH, p_W2T + (size_t)l * DD * FFH, FFH, p_W2part, nullptr,
            FFH, W2SPL, DD, 0, 0, (size_t)B4 * NZ * DD);
    }

    // final LN folds the last layer's W2 partials
    ln768_kernel<false, true><<<B4 * NZ, 256>>>(p_lat, out_g, out_b, out, p_lat);
}